// round 17
// baseline (speedup 1.0000x reference)
#include <cuda_runtime.h>
#include <cuda_fp16.h>
#include <cstdint>

constexpr int N    = 32768;
constexpr int EPER = 16384;
constexpr int T    = 8;
constexpr int E0   = T * EPER;   // 131072 typed edges
constexpr int E    = E0 + N;     // + self loops = 163840
constexpr int H    = 4;
constexpr float NEG = 0.2f;

// ---------------------------- scratch (device globals) ---------------------
__device__ float   g_agg[(size_t)N * 512];   // L3 half agg (aliased)
__device__ float   g_hbuf[(size_t)N * 128];  // L1 output activations (fp32, K=32)
__device__ __half2 g_hbufh2[(size_t)N * 64]; // L2 output (half) for L3 gathers
// score double buffers: A = L1 & L3 scores, B = L2 scores
__device__ float   g_ssrcA[N * H], g_sdstA[N * H];
__device__ float   g_ssrcB[N * H], g_sdstB[N * H];
__device__ float   g_etab[3][(T + 1) * H];
__device__ float   g_usrc[3][512];
__device__ float   g_udst[3][512];
__device__ float   g_wst1[64 * 32];          // L1 fp32 [H*K, dout]
__device__ __half  g_wst2[128 * 128];        // L2 half [dout, H*K] K-major
__device__ __half  g_wst3[512 * 512];        // L3 half [dout, H*K] K-major
__device__ int     g_se[E];                  // dst-sorted packed edges: src | (et<<20)
__device__ int     g_src[E], g_dst[E], g_et[E];
__device__ int     g_deg[N], g_rowptr[N + 1], g_fill[N];

// ---------- ONE setup kernel: graph build + all weight prep (overlapped) ---
__global__ void k_setup(const int* __restrict__ eit,
    const float* __restrict__ W1, const float* __restrict__ as1,
    const float* __restrict__ ad1, const float* __restrict__ We1,
    const float* __restrict__ ae1,
    const float* __restrict__ W2, const float* __restrict__ as2,
    const float* __restrict__ ad2, const float* __restrict__ We2,
    const float* __restrict__ ae2,
    const float* __restrict__ W3, const float* __restrict__ as3,
    const float* __restrict__ ad3, const float* __restrict__ We3,
    const float* __restrict__ ae3) {
    __shared__ float sm[32][33];
    int b = blockIdx.x, tid = threadIdx.x;

    if (b < 640) {
        int e = b * 256 + tid;
        if (e >= E) return;
        int s, d, t;
        if (e < E0) {
            t = e / EPER;
            int i = e - t * EPER;
            s = eit[t * 2 * EPER + i];
            d = eit[t * 2 * EPER + EPER + i];
        } else {
            s = d = e - E0;
            t = T;
        }
        g_src[e] = s; g_dst[e] = d; g_et[e] = t;
        atomicAdd(&g_deg[d], 1);
    } else if (b < 648) {
        int idx = (b - 640) * 256 + tid;         // 2048 = 64*32
        int d = idx % 32, hk = idx / 32;
        int h = hk / 16, k = hk % 16;
        g_wst1[idx] = W1[(size_t)k * 128 + h * 32 + d] * 0.25f;
    } else if (b < 664) {
        int rel = b - 648;
        int h = rel >> 2, dt = rel & 3;
        int ty = tid >> 5, tx = tid & 31;
#pragma unroll
        for (int p = 0; p < 4; p++) {
            int k = p * 8 + ty;
            sm[k][tx] = W2[(size_t)k * 512 + h * 128 + dt * 32 + tx];
        }
        __syncthreads();
#pragma unroll
        for (int p = 0; p < 4; p++) {
            int d = p * 8 + ty;
            g_wst2[(size_t)(dt * 32 + d) * 128 + h * 32 + tx] =
                __float2half(sm[tx][d] * 0.25f);
        }
    } else if (b < 920) {
        int rel = b - 664;                       // 256 = 4h * 4kt * 16dt
        int h = rel >> 6, rem = rel & 63;
        int kt = rem >> 4, dt = rem & 15;
        int ty = tid >> 5, tx = tid & 31;
#pragma unroll
        for (int p = 0; p < 4; p++) {
            int k = p * 8 + ty;
            sm[k][tx] = W3[(size_t)(kt * 32 + k) * 2048 + h * 512 + dt * 32 + tx];
        }
        __syncthreads();
#pragma unroll
        for (int p = 0; p < 4; p++) {
            int d = p * 8 + ty;
            g_wst3[(size_t)(dt * 32 + d) * 512 + h * 128 + kt * 32 + tx] =
                __float2half(sm[tx][d] * 0.25f);
        }
    } else if (b < 1008) {
        int gw = (b - 920) * 8 + (tid >> 5);
        int lane = tid & 31;
        int L, e;
        if (gw < 64)       { L = 0; e = gw; }
        else if (gw < 192) { L = 1; e = gw - 64; }
        else               { L = 2; e = gw - 192; }
        if (L == 2 && e >= 512) return;
        int K    = (L == 0) ? 16 : (L == 1) ? 32 : 128;
        int dout = (L == 0) ? 32 : (L == 1) ? 128 : 512;
        const float* W  = (L == 0) ? W1  : (L == 1) ? W2  : W3;
        const float* as = (L == 0) ? as1 : (L == 1) ? as2 : as3;
        const float* ad = (L == 0) ? ad1 : (L == 1) ? ad2 : ad3;
        int h = e / K, k = e % K;
        const float* wr = W + (size_t)k * (H * dout) + h * dout;
        float vs = 0.f, vd = 0.f;
        for (int d = lane; d < dout; d += 32) {
            float w = wr[d];
            vs += w * as[h * dout + d];
            vd += w * ad[h * dout + d];
        }
#pragma unroll
        for (int o = 16; o > 0; o >>= 1) {
            vs += __shfl_xor_sync(0xffffffffu, vs, o);
            vd += __shfl_xor_sync(0xffffffffu, vd, o);
        }
        if (lane == 0) {
            g_usrc[L][e] = vs;
            g_udst[L][e] = vd;
        }
    } else {
        int L = b - 1008;
        int dout = (L == 0) ? 32 : (L == 1) ? 128 : 512;
        const float* We = (L == 0) ? We1 : (L == 1) ? We2 : We3;
        const float* ae = (L == 0) ? ae1 : (L == 1) ? ae2 : ae3;
        int HC = H * dout;
        int wrp = tid >> 5, lane = tid & 31;
#pragma unroll
        for (int i = 0; i < 4; i++) {
            int e = wrp * 4 + i;
            int t = e >> 2, h = e & 3;
            float s = 0.f;
            for (int c = lane; c < dout; c += 32)
                s += We[t * HC + h * dout + c] * ae[h * dout + c];
#pragma unroll
            for (int o = 16; o > 0; o >>= 1)
                s += __shfl_xor_sync(0xffffffffu, s, o);
            if (lane == 0) {
                sm[t][h] = s;
                g_etab[L][t * H + h] = s;
            }
        }
        __syncthreads();
        if (tid < H) {
            float s = 0.f;
            for (int t = 0; t < T; t++) s += sm[t][tid];
            g_etab[L][T * H + tid] = s * (1.0f / T);
        }
    }
}

// scan also RE-ZEROES g_deg (call-invariant).
__global__ void k_scan() {
    __shared__ int sh[1024];
    int t = threadIdx.x;
    int base = t * 32;
    int loc[32];
    int sum = 0;
#pragma unroll
    for (int i = 0; i < 32; i++) { loc[i] = sum; sum += g_deg[base + i]; g_deg[base + i] = 0; }
    sh[t] = sum;
    __syncthreads();
    for (int off = 1; off < 1024; off <<= 1) {
        int v = (t >= off) ? sh[t - off] : 0;
        __syncthreads();
        if (t >= off) sh[t] += v;
        __syncthreads();
    }
    int prev = (t == 0) ? 0 : sh[t - 1];
#pragma unroll
    for (int i = 0; i < 32; i++) {
        int v = prev + loc[i];
        g_rowptr[base + i] = v;
        g_fill[base + i]   = v;
    }
    if (t == 1023) g_rowptr[N] = sh[1023];
}

// ---- fused scatter + L1 scores (writes buffer A) ---------------------------
__global__ void k_scat_scores(const float* __restrict__ x) {
    int b = blockIdx.x, tid = threadIdx.x;
    if (b < 640) {
        int e = b * 256 + tid;
        if (e >= E) return;
        int pos = atomicAdd(&g_fill[g_dst[e]], 1);
        g_se[pos] = g_src[e] | (g_et[e] << 20);
    } else {
        int gw = (b - 640) * 8 + (tid >> 5);
        int lane = tid & 31, sl = lane & 15;
        int n = gw * 2 + (lane >> 4);
        float xv = x[n * 16 + sl];
        float p[8];
#pragma unroll
        for (int h = 0; h < H; h++) {
            p[h]     = xv * g_usrc[0][h * 16 + sl];
            p[h + 4] = xv * g_udst[0][h * 16 + sl];
        }
#pragma unroll
        for (int o = 8; o > 0; o >>= 1)
#pragma unroll
            for (int i = 0; i < 8; i++)
                p[i] += __shfl_xor_sync(0xffffffffu, p[i], o);
        if (sl < 8) {
            float v = p[sl];
            if (sl < 4) g_ssrcA[n * H + sl] = v;
            else        g_sdstA[n * H + (sl - 4)] = v;
        }
    }
}

// ---- shared edge-softmax helpers ------------------------------------------
__device__ __forceinline__ void warp_softmax(const float* __restrict__ ssrc,
                                             const float* __restrict__ sdst,
                                             int n, int L, int D,
                                             const int* s_pk, float (*s_aw)[H],
                                             int lane) {
    int hh = lane & 3;
    int j0 = lane >> 2;
    float sd = sdst[n * H + hh];
    float m = -1e30f, s = 0.f;
    for (int jj = j0; jj < D; jj += 8) {
        int p = s_pk[jj];
        int src = p & 0xFFFFF, et = p >> 20;
        float a = ssrc[src * H + hh] + sd + g_etab[L][et * H + hh];
        a = (a > 0.f) ? a : NEG * a;
        s_aw[jj][hh] = a;
        float mn = fmaxf(m, a);
        s = s * __expf(m - mn) + __expf(a - mn);
        m = mn;
    }
#pragma unroll
    for (int o = 4; o <= 16; o <<= 1) {
        float m2 = __shfl_xor_sync(0xffffffffu, m, o);
        float s2 = __shfl_xor_sync(0xffffffffu, s, o);
        float mn = fmaxf(m, m2);
        s = s * __expf(m - mn) + s2 * __expf(m2 - mn);
        m = mn;
    }
    float inv = 1.f / s;
    for (int jj = j0; jj < D; jj += 8)
        s_aw[jj][hh] = __expf(s_aw[jj][hh] - m) * inv;
}

__device__ __forceinline__ void warp_softmax_stats(const float* __restrict__ ssrc,
                                                   const float* __restrict__ sdst,
                                                   int n, int L, int D, int b0,
                                                   float* m4, float* i4, int lane) {
    int hh = lane & 3;
    int j0 = lane >> 2;
    float sd = sdst[n * H + hh];
    float m = -1e30f, s = 0.f;
    for (int jj = j0; jj < D; jj += 8) {
        int p = g_se[b0 + jj];
        int src = p & 0xFFFFF, et = p >> 20;
        float a = ssrc[src * H + hh] + sd + g_etab[L][et * H + hh];
        a = (a > 0.f) ? a : NEG * a;
        float mn = fmaxf(m, a);
        s = s * __expf(m - mn) + __expf(a - mn);
        m = mn;
    }
#pragma unroll
    for (int o = 4; o <= 16; o <<= 1) {
        float m2 = __shfl_xor_sync(0xffffffffu, m, o);
        float s2 = __shfl_xor_sync(0xffffffffu, s, o);
        float mn = fmaxf(m, m2);
        s = s * __expf(m - mn) + s2 * __expf(m2 - mn);
        m = mn;
    }
    float inv = 1.f / s;
#pragma unroll
    for (int h4 = 0; h4 < H; h4++) {
        m4[h4] = __shfl_sync(0xffffffffu, m, h4);
        i4[h4] = __shfl_sync(0xffffffffu, inv, h4);
    }
}

// ---- L1 FUSED: edge (reads A) + GEMM 64x32 + L2 scores (writes B) ---------
constexpr int CAP = 64;

__global__ void __launch_bounds__(256)
k_l1_fused(const float* __restrict__ x, const float* __restrict__ bias,
           float* __restrict__ hbuf) {
    __shared__ float s_w1[64][32];
    __shared__ float s_b[32];
    __shared__ int   s_pk[8][CAP];
    __shared__ float s_aw[8][CAP][H];
    __shared__ float s_ag[8][64];

    int tid = threadIdx.x;
    int lane = tid & 31, grp = tid >> 5;
    int n = blockIdx.x * 8 + grp;

    for (int i = tid; i < 2048; i += 256) s_w1[i >> 5][i & 31] = g_wst1[i];
    if (tid < 32) s_b[tid] = bias[tid];
    __syncthreads();

    int b0 = g_rowptr[n], b1 = g_rowptr[n + 1];
    int D = b1 - b0;
    float a0 = 0.f, a1 = 0.f, a2 = 0.f, a3 = 0.f;

    if (D <= CAP) {
        for (int j = lane; j < D; j += 32) s_pk[grp][j] = g_se[b0 + j];
        __syncwarp();
        warp_softmax(g_ssrcA, g_sdstA, n, 0, D, s_pk[grp], s_aw[grp], lane);
        __syncwarp();
        if (lane < 16) {
            for (int jj = 0; jj < D; jj++) {
                int src = s_pk[grp][jj] & 0xFFFFF;
                float v = x[(size_t)src * 16 + lane];
                a0 += s_aw[grp][jj][0] * v;
                a1 += s_aw[grp][jj][1] * v;
                a2 += s_aw[grp][jj][2] * v;
                a3 += s_aw[grp][jj][3] * v;
            }
        }
    } else {
        float m4[H], i4[H];
        warp_softmax_stats(g_ssrcA, g_sdstA, n, 0, D, b0, m4, i4, lane);
        if (lane < 16) {
            float sd4[H];
#pragma unroll
            for (int h4 = 0; h4 < H; h4++) sd4[h4] = g_sdstA[n * H + h4];
            for (int jj = 0; jj < D; jj++) {
                int p = g_se[b0 + jj];
                int src = p & 0xFFFFF, et = p >> 20;
                float v = x[(size_t)src * 16 + lane];
#pragma unroll
                for (int h4 = 0; h4 < H; h4++) {
                    float a = g_ssrcA[src * H + h4] + sd4[h4] + g_etab[0][et * H + h4];
                    a = (a > 0.f) ? a : NEG * a;
                    float w = __expf(a - m4[h4]) * i4[h4];
                    if (h4 == 0) a0 += w * v;
                    else if (h4 == 1) a1 += w * v;
                    else if (h4 == 2) a2 += w * v;
                    else a3 += w * v;
                }
            }
        }
    }

    if (lane < 16) {
        s_ag[grp][lane]      = a0;
        s_ag[grp][16 + lane] = a1;
        s_ag[grp][32 + lane] = a2;
        s_ag[grp][48 + lane] = a3;
    }
    __syncwarp();

    float acc = 0.f;
#pragma unroll 16
    for (int hk = 0; hk < 64; hk++) acc += s_ag[grp][hk] * s_w1[hk][lane];
    acc += s_b[lane];
    acc = fmaxf(acc, 0.f);
    hbuf[(size_t)n * 32 + lane] = acc;

    // fused L2 scores -> buffer B
    float rs[H], rd[H];
#pragma unroll
    for (int h = 0; h < H; h++) {
        rs[h] = acc * g_usrc[1][h * 32 + lane];
        rd[h] = acc * g_udst[1][h * 32 + lane];
#pragma unroll
        for (int o = 16; o > 0; o >>= 1) {
            rs[h] += __shfl_xor_sync(0xffffffffu, rs[h], o);
            rd[h] += __shfl_xor_sync(0xffffffffu, rd[h], o);
        }
    }
    if (lane == 0) {
#pragma unroll
        for (int h = 0; h < H; h++) {
            g_ssrcB[n * H + h] = rs[h];
            g_sdstB[n * H + h] = rd[h];
        }
    }
}

__device__ __forceinline__ uint32_t smem_u32(const void* p) {
    uint32_t a;
    asm("{ .reg .u64 t; cvta.to.shared.u64 t, %1; cvt.u32.u64 %0, t; }" : "=r"(a) : "l"(p));
    return a;
}

// ---- L2 FULLY FUSED: edge agg (reads hbuf, scores B) -> smem A tile,
//      single-K MMA vs wst2, epilogue: half2 out + L3 scores (writes A bufs).
// CTA = 128 nodes. A chunk h holds K-slice [h*32, h*32+32) = head h's agg.
constexpr int SMEM_L2 = (4 * 128 * 40 + 4 * 128 * 40) * 2;   // 81920 B

__global__ void __launch_bounds__(256)
k_l2_fused(const float* __restrict__ hbuf, const float* __restrict__ bias,
           __half2* __restrict__ Ch2, const float* __restrict__ Usrc,
           const float* __restrict__ Udst) {
    extern __shared__ char hsm[];
    __half* Asm = reinterpret_cast<__half*>(hsm);            // 4 x [128][40]
    __half* Bsm = reinterpret_cast<__half*>(hsm) + 4 * 128 * 40;
    __shared__ int   s_pk[8][CAP];
    __shared__ float s_aw[8][CAP][H];

    int tid = threadIdx.x;
    int wid = tid >> 5, lane = tid & 31;
    int bm = blockIdx.x * 128;

    // ---- B: cp.async all 4 K-chunks of wst2 (2048 x 16B) ----
    for (int i = tid; i < 2048; i += 256) {
        int kc = i >> 9, rem = i & 511;
        int row = rem >> 2, q = rem & 3;
        uint32_t dst = smem_u32(&Bsm[kc * 5120 + row * 40 + q * 8]);
        const __half* src = &g_wst2[(size_t)row * 128 + kc * 32 + q * 8];
        asm volatile("cp.async.ca.shared.global [%0], [%1], 16;" :: "r"(dst), "l"(src));
    }
    asm volatile("cp.async.commit_group;");

    // ---- edge phase: each warp handles 16 nodes, writes half agg to Asm ---
    for (int i = 0; i < 16; i++) {
        int nl = wid * 16 + i;
        int n = bm + nl;
        int b0 = g_rowptr[n], b1 = g_rowptr[n + 1];
        int D = b1 - b0;
        float a0 = 0.f, a1 = 0.f, a2 = 0.f, a3 = 0.f;

        if (D <= CAP) {
            for (int j = lane; j < D; j += 32) s_pk[wid][j] = g_se[b0 + j];
            __syncwarp();
            warp_softmax(g_ssrcB, g_sdstB, n, 1, D, s_pk[wid], s_aw[wid], lane);
            __syncwarp();
            int jj = 0;
            for (; jj + 4 <= D; jj += 4) {
                int s0 = s_pk[wid][jj]     & 0xFFFFF;
                int s1 = s_pk[wid][jj + 1] & 0xFFFFF;
                int s2 = s_pk[wid][jj + 2] & 0xFFFFF;
                int s3 = s_pk[wid][jj + 3] & 0xFFFFF;
                float v0 = hbuf[(size_t)s0 * 32 + lane];
                float v1 = hbuf[(size_t)s1 * 32 + lane];
                float v2 = hbuf[(size_t)s2 * 32 + lane];
                float v3 = hbuf[(size_t)s3 * 32 + lane];
                a0 += s_aw[wid][jj][0] * v0 + s_aw[wid][jj + 1][0] * v1
                    + s_aw[wid][jj + 2][0] * v2 + s_aw[wid][jj + 3][0] * v3;
                a1 += s_aw[wid][jj][1] * v0 + s_aw[wid][jj + 1][1] * v1
                    + s_aw[wid][jj + 2][1] * v2 + s_aw[wid][jj + 3][1] * v3;
                a2 += s_aw[wid][jj][2] * v0 + s_aw[wid][jj + 1][2] * v1
                    + s_aw[wid][jj + 2][2] * v2 + s_aw[wid][jj + 3][2] * v3;
                a3 += s_aw[wid][jj][3] * v0 + s_aw[wid][jj + 1][3] * v1
                    + s_aw[wid][jj + 2][3] * v2 + s_aw[wid][jj + 3][3] * v3;
            }
            for (; jj < D; jj++) {
                int src = s_pk[wid][jj] & 0xFFFFF;
                float v = hbuf[(size_t)src * 32 + lane];
                a0 += s_aw[wid][jj][0] * v;
                a1 += s_aw[wid][jj][1] * v;
                a2 += s_aw[wid][jj][2] * v;
                a3 += s_aw[wid][jj][3] * v;
            }
        } else {
            float m4[H], i4[H];
            warp_softmax_stats(g_ssrcB, g_sdstB, n, 1, D, b0, m4, i4, lane);
            float sd4[H];
#pragma unroll
            for (int h4 = 0; h4 < H; h4++) sd4[h4] = g_sdstB[n * H + h4];
            for (int jj = 0; jj < D; jj++) {
                int p = g_se[b0 + jj];
                int src = p & 0xFFFFF, et = p >> 20;
                float v = hbuf[(size_t)src * 32 + lane];
#pragma unroll
                for (int h4 = 0; h4 < H; h4++) {
                    float a = g_ssrcB[src * H + h4] + sd4[h4] + g_etab[1][et * H + h4];
                    a = (a > 0.f) ? a : NEG * a;
                    float w = __expf(a - m4[h4]) * i4[h4];
                    if (h4 == 0) a0 += w * v;
                    else if (h4 == 1) a1 += w * v;
                    else if (h4 == 2) a2 += w * v;
                    else a3 += w * v;
                }
            }
        }

        Asm[0 * 5120 + nl * 40 + lane] = __float2half(a0);
        Asm[1 * 5120 + nl * 40 + lane] = __float2half(a1);
        Asm[2 * 5120 + nl * 40 + lane] = __float2half(a2);
        Asm[3 * 5120 + nl * 40 + lane] = __float2half(a3);
    }

    asm volatile("cp.async.wait_group 0;");
    __syncthreads();

    // ---- MMA: 4 K-chunks, same ordering as the generic GEMM ----
    int wm = (wid >> 2) * 64;
    int wn = (wid & 3) * 32;
    int grp = lane >> 2, tig = lane & 3;
    int mtx = lane >> 3, rin = lane & 7;

    float c[4][4][4];
#pragma unroll
    for (int mt = 0; mt < 4; mt++)
#pragma unroll
        for (int nt = 0; nt < 4; nt++)
#pragma unroll
            for (int q = 0; q < 4; q++) c[mt][nt][q] = 0.f;

#pragma unroll
    for (int it = 0; it < 4; it++) {
        __half* As = Asm + it * 5120;
        __half* Bs = Bsm + it * 5120;
#pragma unroll
        for (int ks = 0; ks < 2; ks++) {
            uint32_t a[4][4], b[4][2];
#pragma unroll
            for (int mt = 0; mt < 4; mt++) {
                int row = wm + mt * 16 + (mtx & 1) * 8 + rin;
                int col = ks * 16 + (mtx >> 1) * 8;
                uint32_t addr = smem_u32(&As[row * 40 + col]);
                asm volatile("ldmatrix.sync.aligned.m8n8.x4.shared.b16 {%0,%1,%2,%3}, [%4];"
                             : "=r"(a[mt][0]), "=r"(a[mt][1]), "=r"(a[mt][2]), "=r"(a[mt][3])
                             : "r"(addr));
            }
#pragma unroll
            for (int np = 0; np < 2; np++) {
                int row = wn + np * 16 + (mtx >> 1) * 8 + rin;
                int col = ks * 16 + (mtx & 1) * 8;
                uint32_t addr = smem_u32(&Bs[row * 40 + col]);
                asm volatile("ldmatrix.sync.aligned.m8n8.x4.shared.b16 {%0,%1,%2,%3}, [%4];"
                             : "=r"(b[np * 2][0]), "=r"(b[np * 2][1]),
                               "=r"(b[np * 2 + 1][0]), "=r"(b[np * 2 + 1][1])
                             : "r"(addr));
            }
#pragma unroll
            for (int mt = 0; mt < 4; mt++)
#pragma unroll
                for (int nt = 0; nt < 4; nt++) {
                    asm volatile(
                        "mma.sync.aligned.m16n8k16.row.col.f32.f16.f16.f32 "
                        "{%0,%1,%2,%3}, {%4,%5,%6,%7}, {%8,%9}, {%0,%1,%2,%3};"
                        : "+f"(c[mt][nt][0]), "+f"(c[mt][nt][1]),
                          "+f"(c[mt][nt][2]), "+f"(c[mt][nt][3])
                        : "r"(a[mt][0]), "r"(a[mt][1]), "r"(a[mt][2]), "r"(a[mt][3]),
                          "r"(b[nt][0]), "r"(b[nt][1]));
                }
        }
    }
    __syncthreads();   // all warps done with Asm/Bsm before s_sc overlay

    float bv[4][2];
#pragma unroll
    for (int nt = 0; nt < 4; nt++) {
        int col = wn + nt * 8 + tig * 2;
        bv[nt][0] = bias[col];
        bv[nt][1] = bias[col + 1];
    }

    // epilogue: relu + half2 out only (fp32 L2 output is dead)
#pragma unroll
    for (int mt = 0; mt < 4; mt++) {
#pragma unroll
        for (int nt = 0; nt < 4; nt++) {
            int col = wn + nt * 8 + tig * 2;
            int r0 = bm + wm + mt * 16 + grp;
            float v00 = fmaxf(c[mt][nt][0] + bv[nt][0], 0.f);
            float v01 = fmaxf(c[mt][nt][1] + bv[nt][1], 0.f);
            float v10 = fmaxf(c[mt][nt][2] + bv[nt][0], 0.f);
            float v11 = fmaxf(c[mt][nt][3] + bv[nt][1], 0.f);
            Ch2[((size_t)r0 * 128 + col) >> 1]       = __floats2half2_rn(v00, v01);
            Ch2[((size_t)(r0 + 8) * 128 + col) >> 1] = __floats2half2_rn(v10, v11);
        }
    }

    // fused L3 scores -> buffer A score arrays
    {
        float* s_sc = reinterpret_cast<float*>(hsm);   // overlays Asm (done)
        for (int i = tid; i < 128 * 8; i += 256) s_sc[i] = 0.f;
        __syncthreads();
#pragma unroll
        for (int h8 = 0; h8 < 8; h8++) {
            const float* U = (h8 < 4) ? (Usrc + h8 * 128) : (Udst + (h8 - 4) * 128);
            float u[4][2];
#pragma unroll
            for (int nt = 0; nt < 4; nt++) {
                int col = wn + nt * 8 + tig * 2;
                u[nt][0] = U[col];
                u[nt][1] = U[col + 1];
            }
#pragma unroll
            for (int mt = 0; mt < 4; mt++) {
                int r0 = wm + mt * 16 + grp;
                float p0 = 0.f, p1 = 0.f;
#pragma unroll
                for (int nt = 0; nt < 4; nt++) {
                    float v00 = fmaxf(c[mt][nt][0] + bv[nt][0], 0.f);
                    float v01 = fmaxf(c[mt][nt][1] + bv[nt][1], 0.f);
                    float v10 = fmaxf(c[mt][nt][2] + bv[nt][0], 0.f);
                    float v11 = fmaxf(c[mt][nt][3] + bv[nt][1], 0.f);
                    p0 += v00 * u[nt][0] + v01 * u[nt][1];
                    p1 += v10 * u[nt][0] + v11 * u[nt][1];
                }
                p0 += __shfl_xor_sync(0xffffffffu, p0, 1);
                p0 += __shfl_xor_sync(0xffffffffu, p0, 2);
                p1 += __shfl_xor_sync(0xffffffffu, p1, 1);
                p1 += __shfl_xor_sync(0xffffffffu, p1, 2);
                if (tig == 0) {
                    atomicAdd(&s_sc[r0 * 8 + h8], p0);
                    atomicAdd(&s_sc[(r0 + 8) * 8 + h8], p1);
                }
            }
        }
        __syncthreads();
        for (int i = tid; i < 128 * 8; i += 256) {
            int r = i >> 3, h8 = i & 7;
            float v = s_sc[i];
            if (h8 < 4) g_ssrcA[(bm + r) * H + h8] = v;
            else        g_sdstA[(bm + r) * H + (h8 - 4)] = v;
        }
    }
}

// ------- L3 edge kernel: warp per node, 8 nodes/256-block, half2 gathers ---
__global__ void __launch_bounds__(256)
k_gat_edge3(const __half2* __restrict__ h2, __half2* __restrict__ agg2) {
    __shared__ int   s_pk[8][CAP];
    __shared__ float s_aw[8][CAP][H];

    int lane = threadIdx.x & 31;
    int grp  = threadIdx.x >> 5;
    int n    = blockIdx.x * 8 + grp;
    int b0 = g_rowptr[n], b1 = g_rowptr[n + 1];
    int D = b1 - b0;

    float ax[H], ay[H], bx[H], by[H];
#pragma unroll
    for (int h4 = 0; h4 < H; h4++) { ax[h4] = 0.f; ay[h4] = 0.f; bx[h4] = 0.f; by[h4] = 0.f; }

    if (D <= CAP) {
        for (int j = lane; j < D; j += 32) s_pk[grp][j] = g_se[b0 + j];
        __syncwarp();
        warp_softmax(g_ssrcA, g_sdstA, n, 2, D, s_pk[grp], s_aw[grp], lane);
        __syncwarp();
        int jj = 0;
        for (; jj + 2 <= D; jj += 2) {
            int s0 = s_pk[grp][jj]     & 0xFFFFF;
            int s1 = s_pk[grp][jj + 1] & 0xFFFFF;
            float2 v0 = __half22float2(h2[(size_t)s0 * 64 + lane]);
            float2 u0 = __half22float2(h2[(size_t)s0 * 64 + 32 + lane]);
            float2 v1 = __half22float2(h2[(size_t)s1 * 64 + lane]);
            float2 u1 = __half22float2(h2[(size_t)s1 * 64 + 32 + lane]);
#pragma unroll
            for (int h4 = 0; h4 < H; h4++) {
                float w0 = s_aw[grp][jj][h4], w1 = s_aw[grp][jj + 1][h4];
                ax[h4] += w0 * v0.x + w1 * v1.x;
                ay[h4] += w0 * v0.y + w1 * v1.y;
                bx[h4] += w0 * u0.x + w1 * u1.x;
                by[h4] += w0 * u0.y + w1 * u1.y;
            }
        }
        for (; jj < D; jj++) {
            int src = s_pk[grp][jj] & 0xFFFFF;
            float2 v = __half22float2(h2[(size_t)src * 64 + lane]);
            float2 u = __half22float2(h2[(size_t)src * 64 + 32 + lane]);
#pragma unroll
            for (int h4 = 0; h4 < H; h4++) {
                float w = s_aw[grp][jj][h4];
                ax[h4] += w * v.x;
                ay[h4] += w * v.y;
                bx[h4] += w * u.x;
                by[h4] += w * u.y;
            }
        }
    } else {
        float m4[H], i4[H];
        warp_softmax_stats(g_ssrcA, g_sdstA, n, 2, D, b0, m4, i4, lane);
        float sd4[H];
#pragma unroll
        for (int h4 = 0; h4 < H; h4++) sd4[h4] = g_sdstA[n * H + h4];
        for (int jj = 0; jj < D; jj++) {
            int p = g_se[b0 + jj];
            int src = p & 0xFFFFF, et = p >> 20;
            float2 v = __half22float2(h2[(size_t)src * 64 + lane]);
            float2 u = __half22float2(h2[(size_t)src * 64 + 32 + lane]);
#pragma unroll
            for (int h4 = 0; h4 < H; h4++) {
                float a = g_ssrcA[src * H + h4] + sd4[h4] + g_etab[2][et * H + h4];
                a = (a > 0.f) ? a : NEG * a;
                float w = __expf(a - m4[h4]) * i4[h4];
                ax[h4] += w * v.x;
                ay[h4] += w * v.y;
                bx[h4] += w * u.x;
                by[h4] += w * u.y;
            }
        }
    }

    size_t base = (size_t)n * 256 + lane;
#pragma unroll
    for (int h4 = 0; h4 < H; h4++) {
        agg2[base + h4 * 64]      = __floats2half2_rn(ax[h4], ay[h4]);
        agg2[base + h4 * 64 + 32] = __floats2half2_rn(bx[h4], by[h4]);
    }
}

// ------- fp16 TC GEMM (L3): 128x128x32 tiles, 3-stage cp.async ring --------
constexpr int STG_BYTES = 128 * 40 * 2 * 2;    // A+B per stage = 20480 B
constexpr int SMEM_HF   = 3 * STG_BYTES;       // 61440 B

__global__ void __launch_bounds__(256, 2)
k_gemm_hf(const __half* __restrict__ A, const __half* __restrict__ Bt,
          const float* __restrict__ bias, float* __restrict__ C,
          int K, int NN) {
    extern __shared__ char hsm[];
    int tid = threadIdx.x;
    int wid = tid >> 5, lane = tid & 31;
    int bm = blockIdx.y * 128, bn = blockIdx.x * 128;
    int wm = (wid >> 2) * 64;
    int wn = (wid & 3) * 32;
    int grp = lane >> 2, tig = lane & 3;

    auto stA = [&](int s) { return reinterpret_cast<__half*>(hsm + s * STG_BYTES); };
    auto stB = [&](int s) { return reinterpret_cast<__half*>(hsm + s * STG_BYTES) + 128 * 40; };

    float c[4][4][4];
#pragma unroll
    for (int mt = 0; mt < 4; mt++)
#pragma unroll
        for (int nt = 0; nt < 4; nt++)
#pragma unroll
            for (int q = 0; q < 4; q++) c[mt][nt][q] = 0.f;

    int nk = K >> 5;

    auto copy_tile = [&](int s, int k0) {
        __half* As = stA(s);
        __half* Bs = stB(s);
#pragma unroll
        for (int i = 0; i < 2; i++) {
            int f = tid + i * 256;
            int m = f >> 2, q = f & 3;
            uint32_t dst = smem_u32(&As[m * 40 + q * 8]);
            const __half* src = &A[(size_t)(bm + m) * K + k0 + q * 8];
            asm volatile("cp.async.ca.shared.global [%0], [%1], 16;" :: "r"(dst), "l"(src));
        }
#pragma unroll
        for (int i = 0; i < 2; i++) {
            int f = tid + i * 256;
            int nrow = f >> 2, q = f & 3;
            uint32_t dst = smem_u32(&Bs[nrow * 40 + q * 8]);
            const __half* src = &Bt[(size_t)(bn + nrow) * K + k0 + q * 8];
            asm volatile("cp.async.ca.shared.global [%0], [%1], 16;" :: "r"(dst), "l"(src));
        }
        asm volatile("cp.async.commit_group;");
    };

    copy_tile(0, 0);
    copy_tile(1, 32);

    int mtx = lane >> 3;
    int rin = lane & 7;

    for (int it = 0; it < nk; it++) {
        int cur = it % 3;
        if (it + 1 < nk) asm volatile("cp.async.wait_group 1;");
        else             asm volatile("cp.async.wait_group 0;");
        __syncthreads();
        if (it + 2 < nk) copy_tile((it + 2) % 3, (it + 2) * 32);

        __half* As = stA(cur);
        __half* Bs = stB(cur);
#pragma unroll
        for (int ks = 0; ks < 2; ks++) {
            uint32_t a[4][4], b[4][2];
#pragma unroll
            for (int mt = 0; mt < 4; mt++) {
                int row = wm + mt * 16 + (mtx & 1) * 8 + rin;
                int col = ks * 16 + (mtx >> 1) * 8;
                uint32_t addr = smem_u32(&As[row * 40 + col]);
                asm volatile("ldmatrix.sync.aligned.m8n8.x4.shared.b16 {%0,%1,%2,%3}, [%4];"
                             : "=r"(a[mt][0]), "=r"(a[mt][1]), "=r"(a[mt][2]), "=r"(a[mt][3])
                             : "r"(addr));
            }
#pragma unroll
            for (int np = 0; np < 2; np++) {
                int row = wn + np * 16 + (mtx >> 1) * 8 + rin;
                int col = ks * 16 + (mtx & 1) * 8;
                uint32_t addr = smem_u32(&Bs[row * 40 + col]);
                asm volatile("ldmatrix.sync.aligned.m8n8.x4.shared.b16 {%0,%1,%2,%3}, [%4];"
                             : "=r"(b[np * 2][0]), "=r"(b[np * 2][1]),
                               "=r"(b[np * 2 + 1][0]), "=r"(b[np * 2 + 1][1])
                             : "r"(addr));
            }
#pragma unroll
            for (int mt = 0; mt < 4; mt++)
#pragma unroll
                for (int nt = 0; nt < 4; nt++) {
                    asm volatile(
                        "mma.sync.aligned.m16n8k16.row.col.f32.f16.f16.f32 "
                        "{%0,%1,%2,%3}, {%4,%5,%6,%7}, {%8,%9}, {%0,%1,%2,%3};"
                        : "+f"(c[mt][nt][0]), "+f"(c[mt][nt][1]),
                          "+f"(c[mt][nt][2]), "+f"(c[mt][nt][3])
                        : "r"(a[mt][0]), "r"(a[mt][1]), "r"(a[mt][2]), "r"(a[mt][3]),
                          "r"(b[nt][0]), "r"(b[nt][1]));
                }
        }
        __syncthreads();
    }

    float bv[4][2];
#pragma unroll
    for (int nt = 0; nt < 4; nt++) {
        int col = bn + wn + nt * 8 + tig * 2;
        bv[nt][0] = bias[col];
        bv[nt][1] = bias[col + 1];
    }

#pragma unroll
    for (int mt = 0; mt < 4; mt++) {
#pragma unroll
        for (int nt = 0; nt < 4; nt++) {
            int col = bn + wn + nt * 8 + tig * 2;
            int r0 = bm + wm + mt * 16 + grp;
            C[(size_t)r0 * NN + col]           = c[mt][nt][0] + bv[nt][0];
            C[(size_t)r0 * NN + col + 1]       = c[mt][nt][1] + bv[nt][1];
            C[(size_t)(r0 + 8) * NN + col]     = c[mt][nt][2] + bv[nt][0];
            C[(size_t)(r0 + 8) * NN + col + 1] = c[mt][nt][3] + bv[nt][1];
        }
    }
}

// ---------------------------------------------------------------------------
extern "C" void kernel_launch(void* const* d_in, const int* in_sizes, int n_in,
                              void* d_out, int out_size) {
    const float* x   = (const float*)d_in[0];
    const int*   eit = (const int*)d_in[1];
    const float* W1  = (const float*)d_in[2];
    const float* We1 = (const float*)d_in[3];
    const float* as1 = (const float*)d_in[4];
    const float* ad1 = (const float*)d_in[5];
    const float* ae1 = (const float*)d_in[6];
    const float* b1  = (const float*)d_in[7];
    const float* W2  = (const float*)d_in[8];
    const float* We2 = (const float*)d_in[9];
    const float* as2 = (const float*)d_in[10];
    const float* ad2 = (const float*)d_in[11];
    const float* ae2 = (const float*)d_in[12];
    const float* b2  = (const float*)d_in[13];
    const float* W3  = (const float*)d_in[14];
    const float* We3 = (const float*)d_in[15];
    const float* as3 = (const float*)d_in[16];
    const float* ad3 = (const float*)d_in[17];
    const float* ae3 = (const float*)d_in[18];
    const float* b3  = (const float*)d_in[19];
    float* out = (float*)d_out;

    float *agg = nullptr, *hbuf = nullptr;
    float *usrc = nullptr, *udst = nullptr;
    __half *wst3 = nullptr;
    __half2 *hbufh2 = nullptr;
    cudaGetSymbolAddress((void**)&agg, g_agg);
    cudaGetSymbolAddress((void**)&hbuf, g_hbuf);
    cudaGetSymbolAddress((void**)&wst3, g_wst3);
    cudaGetSymbolAddress((void**)&hbufh2, g_hbufh2);
    cudaGetSymbolAddress((void**)&usrc, g_usrc);
    cudaGetSymbolAddress((void**)&udst, g_udst);
    const __half* aggh = (const __half*)agg;
    __half2* agg2 = (__half2*)agg;

    cudaFuncSetAttribute(k_gemm_hf, cudaFuncAttributeMaxDynamicSharedMemorySize, SMEM_HF);
    cudaFuncSetAttribute(k_l2_fused, cudaFuncAttributeMaxDynamicSharedMemorySize, SMEM_L2);

    // ---- setup (build+prep), scan, scatter+L1 scores (A) ----
    k_setup<<<1011, 256>>>(eit,
                           W1, as1, ad1, We1, ae1,
                           W2, as2, ad2, We2, ae2,
                           W3, as3, ad3, We3, ae3);
    k_scan<<<1, 1024>>>();
    k_scat_scores<<<640 + 2048, 256>>>(x);

    // ---- layer 1 FUSED: edge(A) + GEMM + L2 scores(B) ----
    k_l1_fused<<<N / 8, 256>>>(x, b1, hbuf);

    // ---- layer 2 FULLY FUSED: edge(B) + MMA + half2 out + L3 scores(A) ----
    k_l2_fused<<<N / 128, 256, SMEM_L2>>>(hbuf, b2, hbufh2,
                                          usrc + 2 * 512, udst + 2 * 512);

    // ---- layer 3: edge(A, warp/node) + TC GEMM -> out ----
    k_gat_edge3<<<N / 8, 256>>>(hbufh2, agg2);
    k_gemm_hf<<<dim3(4, N / 128), 256, SMEM_HF>>>(aggh, wst3, b3, out, 512, 512);
}